// round 1
// baseline (speedup 1.0000x reference)
#include <cuda_runtime.h>
#include <cstdint>
#include <cstddef>

// ---------------- problem constants ----------------
#define T     4
#define WQ    75
#define WAY   5
#define SHOT  5
#define C     640
#define HW    100
#define MS    512              // padded rows per way (500 real + 12 zero)
#define MTOT  (WAY*MS)         // 2560
#define NQ    (WQ*HW)          // 7500
#define NPAD  7552             // 59 * 128
#define BM    128
#define BN    128
#define BK    32
#define SK    36               // smem row stride (floats), 144B = 16B aligned, conflict-free frags

// ---------------- scratch (__device__ globals: no allocation allowed) ----------------
__device__ float g_S[(size_t)T * MTOT * C];       // 26.2 MB, tf32-rounded, K-major
__device__ float g_Q[(size_t)T * NPAD * C];       // 77.3 MB, tf32-rounded, K-major
__device__ float g_meanQ[T * WQ * C];
__device__ float g_meanS[T * WAY * C];
__device__ float g_colsum[T * WAY * NPAD];        // sum over m of P^2, per column

__device__ __forceinline__ float to_tf32(float x) {
    uint32_t r;
    asm("cvt.rna.tf32.f32 %0, %1;" : "=r"(r) : "f"(x));
    return __uint_as_float(r);
}

// ---------------- kernel 1: channel means (warp per (t,row,c)) ----------------
__global__ void means_kernel(const float* __restrict__ qf, const float* __restrict__ sf,
                             float* __restrict__ mq, float* __restrict__ ms) {
    int wid  = (blockIdx.x * blockDim.x + threadIdx.x) >> 5;
    int lane = threadIdx.x & 31;
    const int NQROWS = T * WQ * C;          // 192000
    const int NSROWS = T * WAY * C;         // 12800
    if (wid < NQROWS) {
        const float* p = qf + (size_t)wid * HW;
        float v = p[lane] + p[lane + 32] + p[lane + 64];
        if (lane < 4) v += p[lane + 96];
        #pragma unroll
        for (int o = 16; o; o >>= 1) v += __shfl_xor_sync(~0u, v, o);
        if (!lane) mq[wid] = v * (1.0f / HW);
    } else if (wid < NQROWS + NSROWS) {
        int idx = wid - NQROWS;
        int c   = idx % C;
        int way = (idx / C) % WAY;
        int t   = idx / (C * WAY);
        float v = 0.f;
        #pragma unroll
        for (int sh = 0; sh < SHOT; sh++) {
            const float* p = sf + ((size_t)((t * WAY + way) * SHOT + sh) * C + c) * HW;
            v += p[lane] + p[lane + 32] + p[lane + 64];
            if (lane < 4) v += p[lane + 96];
        }
        #pragma unroll
        for (int o = 16; o; o >>= 1) v += __shfl_xor_sync(~0u, v, o);
        if (!lane) ms[idx] = v * (1.0f / (SHOT * HW));
    }
}

// ---------------- kernel 2: center+transpose support into g_S [t][way*512+m][c] ----------------
__global__ void center_s_kernel(const float* __restrict__ sf, const float* __restrict__ ms,
                                float* __restrict__ out) {
    int i = blockIdx.x * blockDim.x + threadIdx.x;
    if (i >= T * MTOT * C) return;
    int c    = i % C;
    int rest = i / C;
    int m    = rest % MS;
    int way  = (rest / MS) % WAY;
    int t    = rest / (MS * WAY);
    float v = 0.f;
    if (m < SHOT * HW) {
        int sh = m / HW, pos = m % HW;
        float mean = ms[(t * WAY + way) * C + c];
        v = sf[((size_t)((t * WAY + way) * SHOT + sh) * C + c) * HW + pos] - mean;
        v = to_tf32(v);
    }
    out[i] = v;
}

// ---------------- kernel 3: center+transpose query into g_Q [t][q*100+n][c] ----------------
__global__ void center_q_kernel(const float* __restrict__ qf, const float* __restrict__ mq,
                                float* __restrict__ out) {
    int i = blockIdx.x * blockDim.x + threadIdx.x;
    if (i >= T * NPAD * C) return;
    int c    = i % C;
    int rest = i / C;
    int j    = rest % NPAD;
    int t    = rest / NPAD;
    float v = 0.f;
    if (j < NQ) {
        int q = j / HW, n = j % HW;
        float mean = mq[(t * WQ + q) * C + c];
        v = to_tf32(qf[((size_t)(t * WQ + q) * C + c) * HW + n] - mean);
    }
    out[i] = v;
}

// ---------------- kernel 4: zero accumulator ----------------
__global__ void zero_cs_kernel(float* __restrict__ cs) {
    int i = blockIdx.x * blockDim.x + threadIdx.x;
    if (i < T * WAY * NPAD) cs[i] = 0.f;
}

// ---------------- kernel 5: tf32 GEMM P = S @ Q^T with fused column sum-of-squares ----------------
// CTA: 128x128 tile, K chunk 32, double-buffered cp.async. 8 warps in 2(M)x4(N) grid,
// warp tile 64x32 = 4x4 m16n8k8 mma. Epilogue: sum P^2 over the CTA's 128 M rows
// (always within one way since MS=512 = 4*BM), atomicAdd into g_colsum.
__global__ void __launch_bounds__(256) gemm_sq_kernel(const float* __restrict__ A,
                                                      const float* __restrict__ B,
                                                      float* __restrict__ colsum) {
    extern __shared__ float smem[];
    float (*sA)[BM][SK] = (float(*)[BM][SK])smem;
    float (*sB)[BN][SK] = (float(*)[BN][SK])(smem + 2 * BM * SK);

    const int t  = blockIdx.z;
    const int m0 = blockIdx.y * BM;
    const int n0 = blockIdx.x * BN;
    const float* Ap = A + ((size_t)t * MTOT + m0) * C;
    const float* Bp = B + ((size_t)t * NPAD + n0) * C;

    const int tid  = threadIdx.x;
    const int warp = tid >> 5, lane = tid & 31;
    const int wm = warp & 1;          // 0..1 : 64-row half
    const int wn = warp >> 1;         // 0..3 : 32-col quarter
    const int gid = lane >> 2, tig = lane & 3;

    auto issue = [&](int buf, int k0) {
        #pragma unroll
        for (int i = 0; i < 4; i++) {
            int idx = tid + 256 * i;
            int row = idx >> 3;
            int f   = (idx & 7) << 2;
            uint32_t da = (uint32_t)__cvta_generic_to_shared(&sA[buf][row][f]);
            const float* ga = Ap + (size_t)row * C + k0 + f;
            asm volatile("cp.async.cg.shared.global [%0], [%1], 16;\n" :: "r"(da), "l"(ga));
            uint32_t db = (uint32_t)__cvta_generic_to_shared(&sB[buf][row][f]);
            const float* gb = Bp + (size_t)row * C + k0 + f;
            asm volatile("cp.async.cg.shared.global [%0], [%1], 16;\n" :: "r"(db), "l"(gb));
        }
        asm volatile("cp.async.commit_group;\n");
    };

    float acc[4][4][4];
    #pragma unroll
    for (int mi = 0; mi < 4; mi++)
        #pragma unroll
        for (int ni = 0; ni < 4; ni++)
            #pragma unroll
            for (int r = 0; r < 4; r++) acc[mi][ni][r] = 0.f;

    issue(0, 0);

    const int KT = C / BK;   // 20
    for (int kt = 0; kt < KT; kt++) {
        if (kt + 1 < KT) {
            issue((kt + 1) & 1, (kt + 1) * BK);
            asm volatile("cp.async.wait_group 1;\n");
        } else {
            asm volatile("cp.async.wait_group 0;\n");
        }
        __syncthreads();
        int buf = kt & 1;

        #pragma unroll
        for (int ks = 0; ks < 4; ks++) {
            int kk = ks * 8;
            float a[4][4], b[4][2];
            #pragma unroll
            for (int mi = 0; mi < 4; mi++) {
                int r = wm * 64 + mi * 16 + gid;
                a[mi][0] = sA[buf][r    ][kk + tig];
                a[mi][1] = sA[buf][r + 8][kk + tig];
                a[mi][2] = sA[buf][r    ][kk + tig + 4];
                a[mi][3] = sA[buf][r + 8][kk + tig + 4];
            }
            #pragma unroll
            for (int ni = 0; ni < 4; ni++) {
                int cc = wn * 32 + ni * 8 + gid;
                b[ni][0] = sB[buf][cc][kk + tig];
                b[ni][1] = sB[buf][cc][kk + tig + 4];
            }
            #pragma unroll
            for (int mi = 0; mi < 4; mi++)
                #pragma unroll
                for (int ni = 0; ni < 4; ni++) {
                    asm volatile(
                        "mma.sync.aligned.m16n8k8.row.col.f32.tf32.tf32.f32 "
                        "{%0,%1,%2,%3}, {%4,%5,%6,%7}, {%8,%9}, {%0,%1,%2,%3};\n"
                        : "+f"(acc[mi][ni][0]), "+f"(acc[mi][ni][1]),
                          "+f"(acc[mi][ni][2]), "+f"(acc[mi][ni][3])
                        : "r"(__float_as_uint(a[mi][0])), "r"(__float_as_uint(a[mi][1])),
                          "r"(__float_as_uint(a[mi][2])), "r"(__float_as_uint(a[mi][3])),
                          "r"(__float_as_uint(b[ni][0])), "r"(__float_as_uint(b[ni][1])));
                }
        }
        __syncthreads();   // protect the buffer being refilled next iteration
    }

    // -------- fused epilogue: column sum of squares over this CTA's 128 rows --------
    const int way = m0 / MS;               // BM divides MS, so tile lies in one way
    float* cs = colsum + ((size_t)t * WAY + way) * NPAD + n0;
    #pragma unroll
    for (int ni = 0; ni < 4; ni++) {
        float v0 = 0.f, v1 = 0.f;
        #pragma unroll
        for (int mi = 0; mi < 4; mi++) {
            v0 += acc[mi][ni][0] * acc[mi][ni][0] + acc[mi][ni][2] * acc[mi][ni][2];
            v1 += acc[mi][ni][1] * acc[mi][ni][1] + acc[mi][ni][3] * acc[mi][ni][3];
        }
        // reduce across the 8 row-groups (lanes sharing tig): xor over lane bits 2..4
        #pragma unroll
        for (int o = 4; o < 32; o <<= 1) {
            v0 += __shfl_xor_sync(~0u, v0, o);
            v1 += __shfl_xor_sync(~0u, v1, o);
        }
        if (gid == 0) {
            int col = wn * 32 + ni * 8 + tig * 2;
            atomicAdd(&cs[col], v0);
            atomicAdd(&cs[col + 1], v1);
        }
    }
}

// ---------------- kernel 6: /99, LeakyReLU(0.2), conv1d(k=stride=100), +bias ----------------
__global__ void final_kernel(const float* __restrict__ colsum, const float* __restrict__ cw,
                             const float* __restrict__ cb, float* __restrict__ out) {
    int wid  = (blockIdx.x * blockDim.x + threadIdx.x) >> 5;
    int lane = threadIdx.x & 31;
    if (wid >= T * WQ * WAY) return;
    int w = wid % WAY;
    int q = (wid / WAY) % WQ;
    int t = wid / (WAY * WQ);
    const float* cs = colsum + ((size_t)t * WAY + w) * NPAD + q * HW;
    float v = 0.f;
    #pragma unroll
    for (int i = 0; i < 4; i++) {
        int n = lane + 32 * i;
        if (n < HW) {
            float x = cs[n] * (1.0f / 99.0f);
            x = (x >= 0.f) ? x : 0.2f * x;
            v += x * cw[n];
        }
    }
    #pragma unroll
    for (int o = 16; o; o >>= 1) v += __shfl_xor_sync(~0u, v, o);
    if (!lane) out[wid] = v + cb[0];
}

// ---------------- launch ----------------
extern "C" void kernel_launch(void* const* d_in, const int* in_sizes, int n_in,
                              void* d_out, int out_size) {
    const float* qf = (const float*)d_in[0];
    const float* sf = (const float*)d_in[1];
    const float* cw = (const float*)d_in[2];
    const float* cb = (const float*)d_in[3];
    float* out = (float*)d_out;

    float *dS, *dQ, *dMQ, *dMS, *dCS;
    cudaGetSymbolAddress((void**)&dS,  g_S);
    cudaGetSymbolAddress((void**)&dQ,  g_Q);
    cudaGetSymbolAddress((void**)&dMQ, g_meanQ);
    cudaGetSymbolAddress((void**)&dMS, g_meanS);
    cudaGetSymbolAddress((void**)&dCS, g_colsum);

    // 1) means: one warp per (t,row,c) — 192000 + 12800 warps
    {
        int warps = T * WQ * C + T * WAY * C;
        int blocks = (warps * 32 + 255) / 256;
        means_kernel<<<blocks, 256>>>(qf, sf, dMQ, dMS);
    }
    // 2) center+transpose S (includes zero padding rows)
    {
        int n = T * MTOT * C;
        center_s_kernel<<<(n + 255) / 256, 256>>>(sf, dMS, dS);
    }
    // 3) center+transpose Q (includes zero padding cols)
    {
        int n = T * NPAD * C;
        center_q_kernel<<<(n + 255) / 256, 256>>>(qf, dMQ, dQ);
    }
    // 4) zero accumulator
    {
        int n = T * WAY * NPAD;
        zero_cs_kernel<<<(n + 255) / 256, 256>>>(dCS);
    }
    // 5) GEMM + fused sum-of-squares
    {
        const int smem_bytes = (2 * BM * SK + 2 * BN * SK) * (int)sizeof(float); // 73728
        cudaFuncSetAttribute(gemm_sq_kernel, cudaFuncAttributeMaxDynamicSharedMemorySize, smem_bytes);
        dim3 grid(NPAD / BN, MTOT / BM, T);   // (59, 20, 4)
        gemm_sq_kernel<<<grid, 256, smem_bytes>>>(dS, dQ, dCS);
    }
    // 6) final score
    {
        int warps = T * WQ * WAY;             // 1500
        int blocks = (warps * 32 + 255) / 256;
        final_kernel<<<blocks, 256>>>(dCS, cw, cb, out);
    }
}

// round 3
// speedup vs baseline: 2.9760x; 2.9760x over previous
#include <cuda_runtime.h>
#include <cuda_fp16.h>
#include <cstdint>
#include <cstddef>

// ---------------- problem constants ----------------
#define T     4
#define WQ    75
#define WAY   5
#define SHOT  5
#define C     640
#define HW    100
#define MS    512               // padded rows per way (500 real + 12 zero)
#define MTOT  (WAY*MS)          // 2560
#define NQ    (WQ*HW)           // 7500
#define NPAD  7680              // 30 * 256
#define BM    128
#define BN    256
#define BKH   64                // K halves per chunk => 128B smem rows
#define KT    (C/BKH)           // 10
#define STAGES 3

#define A_BYTES    (BM*128)     // 16384
#define B_BYTES    (BN*128)     // 32768
#define STAGE_BYTES (A_BYTES + B_BYTES)              // 49152
#define SMEM_TOTAL  (STAGES*STAGE_BYTES)             // 147456

#define SWZ(o) ((o) ^ (((o) >> 3) & 0x70))
#define WAITG(n) asm volatile("cp.async.wait_group %0;" :: "n"(n))

__device__ __forceinline__ uint32_t smem_u32(const void* p) {
    uint32_t a;
    asm("{ .reg .u64 t; cvta.to.shared.u64 t, %1; cvt.u32.u64 %0, t; }" : "=r"(a) : "l"(p));
    return a;
}

// ---------------- scratch (__device__ globals) ----------------
__device__ __align__(256) __half g_S16[(size_t)T * MTOT * C];   // 13.1 MB
__device__ __align__(256) __half g_Q16[(size_t)T * NPAD * C];   // 39.3 MB
__device__ float g_meanQ[T * WQ * C];
__device__ float g_meanS[T * WAY * C];
__device__ float g_colsum[T * WAY * NPAD];

// ---------------- kernel 1: channel means ----------------
__global__ void means_kernel(const float* __restrict__ qf, const float* __restrict__ sf,
                             float* __restrict__ mq, float* __restrict__ ms) {
    int wid  = (blockIdx.x * blockDim.x + threadIdx.x) >> 5;
    int lane = threadIdx.x & 31;
    const int NQROWS = T * WQ * C;
    const int NSROWS = T * WAY * C;
    if (wid < NQROWS) {
        const float* p = qf + (size_t)wid * HW;
        float v = p[lane] + p[lane + 32] + p[lane + 64];
        if (lane < 4) v += p[lane + 96];
        #pragma unroll
        for (int o = 16; o; o >>= 1) v += __shfl_xor_sync(~0u, v, o);
        if (!lane) mq[wid] = v * (1.0f / HW);
    } else if (wid < NQROWS + NSROWS) {
        int idx = wid - NQROWS;
        int c   = idx % C;
        int way = (idx / C) % WAY;
        int t   = idx / (C * WAY);
        float v = 0.f;
        #pragma unroll
        for (int sh = 0; sh < SHOT; sh++) {
            const float* p = sf + ((size_t)((t * WAY + way) * SHOT + sh) * C + c) * HW;
            v += p[lane] + p[lane + 32] + p[lane + 64];
            if (lane < 4) v += p[lane + 96];
        }
        #pragma unroll
        for (int o = 16; o; o >>= 1) v += __shfl_xor_sync(~0u, v, o);
        if (!lane) ms[idx] = v * (1.0f / (SHOT * HW));
    }
}

// ---------------- kernel 2: center+transpose support -> fp16 K-major ----------------
__global__ void center_s_kernel(const float* __restrict__ sf, const float* __restrict__ ms,
                                __half* __restrict__ out) {
    int i = blockIdx.x * blockDim.x + threadIdx.x;         // over half2 pairs
    const int NP = T * MTOT * (C / 2);
    if (i >= NP) return;
    int c2   = i % (C / 2);
    int rest = i / (C / 2);
    int m    = rest % MS;
    int way  = (rest / MS) % WAY;
    int t    = rest / (MS * WAY);
    int c = c2 * 2;
    float v0 = 0.f, v1 = 0.f;
    if (m < SHOT * HW) {
        int sh = m / HW, pos = m % HW;
        size_t base = ((size_t)((t * WAY + way) * SHOT + sh) * C + c) * HW + pos;
        v0 = sf[base]      - ms[(t * WAY + way) * C + c];
        v1 = sf[base + HW] - ms[(t * WAY + way) * C + c + 1];
    }
    ((__half2*)out)[i] = __floats2half2_rn(v0, v1);
}

// ---------------- kernel 3: center+transpose query -> fp16 K-major ----------------
__global__ void center_q_kernel(const float* __restrict__ qf, const float* __restrict__ mq,
                                __half* __restrict__ out) {
    int i = blockIdx.x * blockDim.x + threadIdx.x;
    const int NP = T * NPAD * (C / 2);
    if (i >= NP) return;
    int c2   = i % (C / 2);
    int rest = i / (C / 2);
    int j    = rest % NPAD;
    int t    = rest / NPAD;
    int c = c2 * 2;
    float v0 = 0.f, v1 = 0.f;
    if (j < NQ) {
        int q = j / HW, n = j % HW;
        size_t base = ((size_t)(t * WQ + q) * C + c) * HW + n;
        v0 = qf[base]      - mq[(t * WQ + q) * C + c];
        v1 = qf[base + HW] - mq[(t * WQ + q) * C + c + 1];
    }
    ((__half2*)out)[i] = __floats2half2_rn(v0, v1);
}

// ---------------- kernel 4: zero accumulator ----------------
__global__ void zero_cs_kernel(float* __restrict__ cs) {
    int i = blockIdx.x * blockDim.x + threadIdx.x;
    if (i < T * WAY * NPAD) cs[i] = 0.f;
}

// ---------------- kernel 5: fp16 HMMA GEMM (128x256) + fused column sum-of-squares ----------------
// 8 warps: 2(M) x 4(N), warp tile 64x64, mma.sync.m16n8k16, ldmatrix.x4 fragments,
// SW128-swizzled smem, 3-stage cp.async pipeline.
__global__ void __launch_bounds__(256, 1) gemm_hmma_kernel(const __half* __restrict__ A,
                                                           const __half* __restrict__ B,
                                                           float* __restrict__ colsum) {
    extern __shared__ char smem[];
    const uint32_t sb = smem_u32(smem);

    const int tid  = threadIdx.x;
    const int warp = tid >> 5, lane = tid & 31;
    const int wm = warp & 1;          // 0..1 : 64-row half (M)
    const int wn = warp >> 1;         // 0..3 : 64-col quarter (N)
    const int gid = lane >> 2, tig = lane & 3;

    const int t  = blockIdx.z;
    const int m0 = blockIdx.y * BM;
    const int n0 = blockIdx.x * BN;
    const __half* Ap = A + ((size_t)t * MTOT + m0) * C;
    const __half* Bp = B + ((size_t)t * NPAD + n0) * C;

    // per-thread ldmatrix address components
    const int arow = lane & 15;                 // A: rows m..m+15 ; +8-row matrix second
    const int akof = (lane >> 4) * 16;          // A: k halves 0..7 then 8..15 (bytes)
    const int brow = ((lane >> 4) << 3) | (lane & 7);   // B: n rows, +8 for matrices 2,3
    const int bkof = ((lane >> 3) & 1) * 16;    // B: k bytes 0 / 16

    auto issue = [&](int kc) {
        const int s  = kc % STAGES;
        const int k0 = kc * BKH;
        const uint32_t sA = sb + s * STAGE_BYTES;
        const uint32_t sB = sA + A_BYTES;
        #pragma unroll
        for (int it = 0; it < 4; it++) {               // A: 1024 x 16B
            int i   = tid + it * 256;
            int row = i >> 3, ch = i & 7;
            uint32_t dst = sA + SWZ(row * 128 + ch * 16);
            const __half* src = Ap + (size_t)row * C + k0 + ch * 8;
            asm volatile("cp.async.cg.shared.global [%0], [%1], 16;" :: "r"(dst), "l"(src));
        }
        #pragma unroll
        for (int it = 0; it < 8; it++) {               // B: 2048 x 16B
            int i   = tid + it * 256;
            int row = i >> 3, ch = i & 7;
            uint32_t dst = sB + SWZ(row * 128 + ch * 16);
            const __half* src = Bp + (size_t)row * C + k0 + ch * 8;
            asm volatile("cp.async.cg.shared.global [%0], [%1], 16;" :: "r"(dst), "l"(src));
        }
        asm volatile("cp.async.commit_group;");
    };

    float acc[4][8][4];
    #pragma unroll
    for (int mi = 0; mi < 4; mi++)
        #pragma unroll
        for (int ni = 0; ni < 8; ni++)
            #pragma unroll
            for (int r = 0; r < 4; r++) acc[mi][ni][r] = 0.f;

    issue(0); issue(1);

    for (int kc = 0; kc < KT; kc++) {
        if (kc + 2 < KT)      { issue(kc + 2); WAITG(2); }
        else if (kc + 1 < KT) { WAITG(1); }
        else                  { WAITG(0); }
        __syncthreads();

        const uint32_t sA = sb + (kc % STAGES) * STAGE_BYTES;
        const uint32_t sB = sA + A_BYTES;

        #pragma unroll
        for (int ks = 0; ks < 4; ks++) {               // 4 x k16 per chunk
            const int kb = ks * 32;                    // byte offset of k16 step
            uint32_t a[4][4], b[8][2];
            #pragma unroll
            for (int mi = 0; mi < 4; mi++) {
                uint32_t addr = sA + SWZ((wm * 64 + mi * 16 + arow) * 128 + kb + akof);
                asm volatile("ldmatrix.sync.aligned.m8n8.x4.shared.b16 {%0,%1,%2,%3}, [%4];"
                             : "=r"(a[mi][0]), "=r"(a[mi][1]), "=r"(a[mi][2]), "=r"(a[mi][3])
                             : "r"(addr));
            }
            #pragma unroll
            for (int nj = 0; nj < 4; nj++) {           // each x4 covers two n8 frags
                uint32_t addr = sB + SWZ((wn * 64 + nj * 16 + brow) * 128 + kb + bkof);
                asm volatile("ldmatrix.sync.aligned.m8n8.x4.shared.b16 {%0,%1,%2,%3}, [%4];"
                             : "=r"(b[nj*2][0]), "=r"(b[nj*2][1]),
                               "=r"(b[nj*2+1][0]), "=r"(b[nj*2+1][1])
                             : "r"(addr));
            }
            #pragma unroll
            for (int mi = 0; mi < 4; mi++)
                #pragma unroll
                for (int ni = 0; ni < 8; ni++) {
                    asm volatile(
                        "mma.sync.aligned.m16n8k16.row.col.f32.f16.f16.f32 "
                        "{%0,%1,%2,%3}, {%4,%5,%6,%7}, {%8,%9}, {%0,%1,%2,%3};"
                        : "+f"(acc[mi][ni][0]), "+f"(acc[mi][ni][1]),
                          "+f"(acc[mi][ni][2]), "+f"(acc[mi][ni][3])
                        : "r"(a[mi][0]), "r"(a[mi][1]), "r"(a[mi][2]), "r"(a[mi][3]),
                          "r"(b[ni][0]), "r"(b[ni][1]));
                }
        }
        __syncthreads();
    }

    // -------- fused epilogue: column sum of squares over this CTA's 128 rows --------
    const int way = m0 / MS;               // BM divides MS -> tile lies in one way
    float* cs = colsum + ((size_t)t * WAY + way) * NPAD + n0;
    #pragma unroll
    for (int ni = 0; ni < 8; ni++) {
        float v0 = 0.f, v1 = 0.f;
        #pragma unroll
        for (int mi = 0; mi < 4; mi++) {
            v0 += acc[mi][ni][0] * acc[mi][ni][0] + acc[mi][ni][2] * acc[mi][ni][2];
            v1 += acc[mi][ni][1] * acc[mi][ni][1] + acc[mi][ni][3] * acc[mi][ni][3];
        }
        #pragma unroll
        for (int o = 4; o < 32; o <<= 1) {
            v0 += __shfl_xor_sync(~0u, v0, o);
            v1 += __shfl_xor_sync(~0u, v1, o);
        }
        if (gid == 0) {
            int col = wn * 64 + ni * 8 + tig * 2;
            atomicAdd(&cs[col], v0);
            atomicAdd(&cs[col + 1], v1);
        }
    }
}

// ---------------- kernel 6: /99, LeakyReLU(0.2), conv1d(k=stride=100), +bias ----------------
__global__ void final_kernel(const float* __restrict__ colsum, const float* __restrict__ cw,
                             const float* __restrict__ cb, float* __restrict__ out) {
    int wid  = (blockIdx.x * blockDim.x + threadIdx.x) >> 5;
    int lane = threadIdx.x & 31;
    if (wid >= T * WQ * WAY) return;
    int w = wid % WAY;
    int q = (wid / WAY) % WQ;
    int t = wid / (WAY * WQ);
    const float* cs = colsum + ((size_t)t * WAY + w) * NPAD + q * HW;
    float v = 0.f;
    #pragma unroll
    for (int i = 0; i < 4; i++) {
        int n = lane + 32 * i;
        if (n < HW) {
            float x = cs[n] * (1.0f / 99.0f);
            x = (x >= 0.f) ? x : 0.2f * x;
            v += x * cw[n];
        }
    }
    #pragma unroll
    for (int o = 16; o; o >>= 1) v += __shfl_xor_sync(~0u, v, o);
    if (!lane) out[wid] = v + cb[0];
}

// ---------------- launch ----------------
extern "C" void kernel_launch(void* const* d_in, const int* in_sizes, int n_in,
                              void* d_out, int out_size) {
    const float* qf = (const float*)d_in[0];
    const float* sf = (const float*)d_in[1];
    const float* cw = (const float*)d_in[2];
    const float* cb = (const float*)d_in[3];
    float* out = (float*)d_out;

    __half *dS, *dQ;
    float *dMQ, *dMS, *dCS;
    cudaGetSymbolAddress((void**)&dS,  g_S16);
    cudaGetSymbolAddress((void**)&dQ,  g_Q16);
    cudaGetSymbolAddress((void**)&dMQ, g_meanQ);
    cudaGetSymbolAddress((void**)&dMS, g_meanS);
    cudaGetSymbolAddress((void**)&dCS, g_colsum);

    {   // 1) means
        int warps = T * WQ * C + T * WAY * C;
        int blocks = (warps * 32 + 255) / 256;
        means_kernel<<<blocks, 256>>>(qf, sf, dMQ, dMS);
    }
    {   // 2) center+transpose S -> fp16
        int n = T * MTOT * (C / 2);
        center_s_kernel<<<(n + 255) / 256, 256>>>(sf, dMS, dS);
    }
    {   // 3) center+transpose Q -> fp16
        int n = T * NPAD * (C / 2);
        center_q_kernel<<<(n + 255) / 256, 256>>>(qf, dMQ, dQ);
    }
    {   // 4) zero accumulator
        int n = T * WAY * NPAD;
        zero_cs_kernel<<<(n + 255) / 256, 256>>>(dCS);
    }
    {   // 5) fp16 HMMA GEMM + fused sum-of-squares
        cudaFuncSetAttribute(gemm_hmma_kernel, cudaFuncAttributeMaxDynamicSharedMemorySize, SMEM_TOTAL);
        dim3 grid(NPAD / BN, MTOT / BM, T);   // (30, 20, 4)
        gemm_hmma_kernel<<<grid, 256, SMEM_TOTAL>>>(dS, dQ, dCS);
    }
    {   // 6) final score
        int warps = T * WQ * WAY;
        int blocks = (warps * 32 + 255) / 256;
        final_kernel<<<blocks, 256>>>(dCS, cw, cb, out);
    }
}

// round 4
// speedup vs baseline: 3.8450x; 1.2920x over previous
#include <cuda_runtime.h>
#include <cuda_fp16.h>
#include <cstdint>
#include <cstddef>

// ---------------- problem constants ----------------
#define T     4
#define WQ    75
#define WAY   5
#define SHOT  5
#define WS    (WAY*SHOT)        // 25
#define C     640
#define HW    100
#define MS    512               // padded rows per way (500 real + 12 zero)
#define MTOT  (WAY*MS)          // 2560
#define NQ    (WQ*HW)           // 7500
#define NPAD  7680              // 30 * 256
#define BM    128
#define BN    256
#define BKH   64                // K halves per chunk => 128B smem rows
#define KT    (C/BKH)           // 10
#define STAGES 3

#define A_BYTES    (BM*128)     // 16384
#define B_BYTES    (BN*128)     // 32768
#define STAGE_BYTES (A_BYTES + B_BYTES)              // 49152
#define SMEM_TOTAL  (STAGES*STAGE_BYTES)             // 147456

#define SWZ(o) ((o) ^ (((o) >> 3) & 0x70))
#define WAITG(n) asm volatile("cp.async.wait_group %0;" :: "n"(n))

__device__ __forceinline__ uint32_t smem_u32(const void* p) {
    uint32_t a;
    asm("{ .reg .u64 t; cvta.to.shared.u64 t, %1; cvt.u32.u64 %0, t; }" : "=r"(a) : "l"(p));
    return a;
}

// ---------------- scratch (__device__ globals) ----------------
__device__ __align__(256) __half g_S16[(size_t)T * MTOT * C];   // 13.1 MB
__device__ __align__(256) __half g_Q16[(size_t)T * NPAD * C];   // 39.3 MB
__device__ float g_meanS[T * WAY * C];
__device__ float g_colsum[T * WAY * NPAD];

// ---------------- kernel 1: support channel means (warp per (t,way,c)) ----------------
__global__ void means_s_kernel(const float* __restrict__ sf, float* __restrict__ ms) {
    int wid  = (blockIdx.x * blockDim.x + threadIdx.x) >> 5;
    int lane = threadIdx.x & 31;
    if (wid >= T * WAY * C) return;
    int c   = wid % C;
    int way = (wid / C) % WAY;
    int t   = wid / (C * WAY);
    float v = 0.f;
    #pragma unroll
    for (int sh = 0; sh < SHOT; sh++) {
        const float* p = sf + ((size_t)((t * WAY + way) * SHOT + sh) * C + c) * HW;
        v += p[lane] + p[lane + 32] + p[lane + 64];
        if (lane < 4) v += p[lane + 96];
    }
    #pragma unroll
    for (int o = 16; o; o >>= 1) v += __shfl_xor_sync(~0u, v, o);
    if (!lane) ms[wid] = v * (1.0f / (SHOT * HW));
}

// ---------------- kernel 2: coalesced center+transpose support -> fp16 K-major ----------------
// block per (t, ws, 64-channel chunk): contiguous 64x100 load, half2 transposed store.
__global__ void __launch_bounds__(256) center_s_kernel(const float* __restrict__ sf,
                                                       const float* __restrict__ ms,
                                                       __half* __restrict__ out) {
    __shared__ float tile[64 * 101];
    int b  = blockIdx.x;
    int cc = b % (C / 64);
    int ws = (b / (C / 64)) % WS;
    int t  = b / ((C / 64) * WS);
    int way = ws / SHOT, sh = ws % SHOT;
    int c0 = cc * 64;
    const float* src = sf + ((size_t)(t * WS + ws) * C + c0) * HW;
    int tid = threadIdx.x;
    #pragma unroll
    for (int i = 0; i < 25; i++) {
        int idx = tid + i * 256;
        tile[(idx / 100) * 101 + (idx % 100)] = src[idx];
    }
    __syncthreads();
    // write transposed: row j = way*512 + sh*100 + n, cols [c0, c0+64), half2 over c
    const float* mrow = ms + (t * WAY + way) * C + c0;
    __half2* dst = (__half2*)(out + ((size_t)t * MTOT + way * MS + sh * HW) * C + c0);
    for (int i = tid; i < 32 * HW; i += 256) {
        int n = i / 32, cp = i % 32;
        float m0 = mrow[cp * 2], m1 = mrow[cp * 2 + 1];
        float v0 = tile[(cp * 2) * 101 + n] - m0;
        float v1 = tile[(cp * 2 + 1) * 101 + n] - m1;
        dst[(size_t)n * (C / 2) + cp] = __floats2half2_rn(v0, v1);
    }
}

// ---------------- kernel 3: coalesced center(fused mean)+transpose query -> fp16 ----------------
__global__ void __launch_bounds__(256) center_q_kernel(const float* __restrict__ qf,
                                                       __half* __restrict__ out) {
    __shared__ float tile[64 * 101];
    __shared__ float mean[64];
    int b  = blockIdx.x;
    int cc = b % (C / 64);
    int q  = (b / (C / 64)) % WQ;
    int t  = b / ((C / 64) * WQ);
    int c0 = cc * 64;
    const float* src = qf + ((size_t)(t * WQ + q) * C + c0) * HW;
    int tid = threadIdx.x, warp = tid >> 5, lane = tid & 31;
    #pragma unroll
    for (int i = 0; i < 25; i++) {
        int idx = tid + i * 256;
        tile[(idx / 100) * 101 + (idx % 100)] = src[idx];
    }
    __syncthreads();
    // fused per-channel means over the 100 spatial positions
    #pragma unroll
    for (int r = warp; r < 64; r += 8) {
        const float* row = &tile[r * 101];
        float v = row[lane] + row[lane + 32] + row[lane + 64];
        if (lane < 4) v += row[lane + 96];
        #pragma unroll
        for (int o = 16; o; o >>= 1) v += __shfl_xor_sync(~0u, v, o);
        if (!lane) mean[r] = v * (1.0f / HW);
    }
    __syncthreads();
    __half2* dst = (__half2*)(out + ((size_t)t * NPAD + q * HW) * C + c0);
    for (int i = tid; i < 32 * HW; i += 256) {
        int n = i / 32, cp = i % 32;
        float v0 = tile[(cp * 2) * 101 + n] - mean[cp * 2];
        float v1 = tile[(cp * 2 + 1) * 101 + n] - mean[cp * 2 + 1];
        dst[(size_t)n * (C / 2) + cp] = __floats2half2_rn(v0, v1);
    }
}

// ---------------- kernel 4: zero the padding rows of g_S16 / g_Q16 ----------------
__global__ void pad_kernel(__half* __restrict__ S, __half* __restrict__ Q) {
    const int NS = T * WAY * (MS - SHOT * HW) * (C / 2);   // 76800 half2
    const int NQP = T * (NPAD - NQ) * (C / 2);             // 230400 half2
    int i = blockIdx.x * blockDim.x + threadIdx.x;
    if (i < NS) {
        int cp = i % (C / 2);
        int r  = (i / (C / 2)) % (MS - SHOT * HW);
        int wy = (i / ((C / 2) * (MS - SHOT * HW))) % WAY;
        int t  = i / ((C / 2) * (MS - SHOT * HW) * WAY);
        ((__half2*)S)[((size_t)t * MTOT + wy * MS + SHOT * HW + r) * (C / 2) + cp] =
            __floats2half2_rn(0.f, 0.f);
    } else if (i < NS + NQP) {
        int j = i - NS;
        int cp = j % (C / 2);
        int r  = (j / (C / 2)) % (NPAD - NQ);
        int t  = j / ((C / 2) * (NPAD - NQ));
        ((__half2*)Q)[((size_t)t * NPAD + NQ + r) * (C / 2) + cp] =
            __floats2half2_rn(0.f, 0.f);
    }
}

// ---------------- kernel 5: zero accumulator ----------------
__global__ void zero_cs_kernel(float* __restrict__ cs) {
    int i = blockIdx.x * blockDim.x + threadIdx.x;
    if (i < T * WAY * NPAD) cs[i] = 0.f;
}

// ---------------- kernel 6: fp16 HMMA GEMM (128x256) + fused column sum-of-squares ----------------
__global__ void __launch_bounds__(256, 1) gemm_hmma_kernel(const __half* __restrict__ A,
                                                           const __half* __restrict__ B,
                                                           float* __restrict__ colsum) {
    extern __shared__ char smem[];
    const uint32_t sb = smem_u32(smem);

    const int tid  = threadIdx.x;
    const int warp = tid >> 5, lane = tid & 31;
    const int wm = warp & 1;          // 0..1 : 64-row half (M)
    const int wn = warp >> 1;         // 0..3 : 64-col quarter (N)
    const int gid = lane >> 2, tig = lane & 3;

    const int t  = blockIdx.z;
    const int m0 = blockIdx.y * BM;
    const int n0 = blockIdx.x * BN;
    const __half* Ap = A + ((size_t)t * MTOT + m0) * C;
    const __half* Bp = B + ((size_t)t * NPAD + n0) * C;

    const int arow = lane & 15;
    const int akof = (lane >> 4) * 16;
    const int brow = ((lane >> 4) << 3) | (lane & 7);
    const int bkof = ((lane >> 3) & 1) * 16;

    auto issue = [&](int kc) {
        const int s  = kc % STAGES;
        const int k0 = kc * BKH;
        const uint32_t sA = sb + s * STAGE_BYTES;
        const uint32_t sB = sA + A_BYTES;
        #pragma unroll
        for (int it = 0; it < 4; it++) {
            int i   = tid + it * 256;
            int row = i >> 3, ch = i & 7;
            uint32_t dst = sA + SWZ(row * 128 + ch * 16);
            const __half* src = Ap + (size_t)row * C + k0 + ch * 8;
            asm volatile("cp.async.cg.shared.global [%0], [%1], 16;" :: "r"(dst), "l"(src));
        }
        #pragma unroll
        for (int it = 0; it < 8; it++) {
            int i   = tid + it * 256;
            int row = i >> 3, ch = i & 7;
            uint32_t dst = sB + SWZ(row * 128 + ch * 16);
            const __half* src = Bp + (size_t)row * C + k0 + ch * 8;
            asm volatile("cp.async.cg.shared.global [%0], [%1], 16;" :: "r"(dst), "l"(src));
        }
        asm volatile("cp.async.commit_group;");
    };

    float acc[4][8][4];
    #pragma unroll
    for (int mi = 0; mi < 4; mi++)
        #pragma unroll
        for (int ni = 0; ni < 8; ni++)
            #pragma unroll
            for (int r = 0; r < 4; r++) acc[mi][ni][r] = 0.f;

    issue(0); issue(1);

    for (int kc = 0; kc < KT; kc++) {
        if (kc + 2 < KT)      { issue(kc + 2); WAITG(2); }
        else if (kc + 1 < KT) { WAITG(1); }
        else                  { WAITG(0); }
        __syncthreads();

        const uint32_t sA = sb + (kc % STAGES) * STAGE_BYTES;
        const uint32_t sB = sA + A_BYTES;

        #pragma unroll
        for (int ks = 0; ks < 4; ks++) {
            const int kb = ks * 32;
            uint32_t a[4][4], b[8][2];
            #pragma unroll
            for (int mi = 0; mi < 4; mi++) {
                uint32_t addr = sA + SWZ((wm * 64 + mi * 16 + arow) * 128 + kb + akof);
                asm volatile("ldmatrix.sync.aligned.m8n8.x4.shared.b16 {%0,%1,%2,%3}, [%4];"
                             : "=r"(a[mi][0]), "=r"(a[mi][1]), "=r"(a[mi][2]), "=r"(a[mi][3])
                             : "r"(addr));
            }
            #pragma unroll
            for (int nj = 0; nj < 4; nj++) {
                uint32_t addr = sB + SWZ((wn * 64 + nj * 16 + brow) * 128 + kb + bkof);
                asm volatile("ldmatrix.sync.aligned.m8n8.x4.shared.b16 {%0,%1,%2,%3}, [%4];"
                             : "=r"(b[nj*2][0]), "=r"(b[nj*2][1]),
                               "=r"(b[nj*2+1][0]), "=r"(b[nj*2+1][1])
                             : "r"(addr));
            }
            #pragma unroll
            for (int mi = 0; mi < 4; mi++)
                #pragma unroll
                for (int ni = 0; ni < 8; ni++) {
                    asm volatile(
                        "mma.sync.aligned.m16n8k16.row.col.f32.f16.f16.f32 "
                        "{%0,%1,%2,%3}, {%4,%5,%6,%7}, {%8,%9}, {%0,%1,%2,%3};"
                        : "+f"(acc[mi][ni][0]), "+f"(acc[mi][ni][1]),
                          "+f"(acc[mi][ni][2]), "+f"(acc[mi][ni][3])
                        : "r"(a[mi][0]), "r"(a[mi][1]), "r"(a[mi][2]), "r"(a[mi][3]),
                          "r"(b[ni][0]), "r"(b[ni][1]));
                }
        }
        __syncthreads();
    }

    const int way = m0 / MS;
    float* cs = colsum + ((size_t)t * WAY + way) * NPAD + n0;
    #pragma unroll
    for (int ni = 0; ni < 8; ni++) {
        float v0 = 0.f, v1 = 0.f;
        #pragma unroll
        for (int mi = 0; mi < 4; mi++) {
            v0 += acc[mi][ni][0] * acc[mi][ni][0] + acc[mi][ni][2] * acc[mi][ni][2];
            v1 += acc[mi][ni][1] * acc[mi][ni][1] + acc[mi][ni][3] * acc[mi][ni][3];
        }
        #pragma unroll
        for (int o = 4; o < 32; o <<= 1) {
            v0 += __shfl_xor_sync(~0u, v0, o);
            v1 += __shfl_xor_sync(~0u, v1, o);
        }
        if (gid == 0) {
            int col = wn * 64 + ni * 8 + tig * 2;
            atomicAdd(&cs[col], v0);
            atomicAdd(&cs[col + 1], v1);
        }
    }
}

// ---------------- kernel 7: /99, LeakyReLU(0.2), conv1d(k=stride=100), +bias ----------------
__global__ void final_kernel(const float* __restrict__ colsum, const float* __restrict__ cw,
                             const float* __restrict__ cb, float* __restrict__ out) {
    int wid  = (blockIdx.x * blockDim.x + threadIdx.x) >> 5;
    int lane = threadIdx.x & 31;
    if (wid >= T * WQ * WAY) return;
    int w = wid % WAY;
    int q = (wid / WAY) % WQ;
    int t = wid / (WAY * WQ);
    const float* cs = colsum + ((size_t)t * WAY + w) * NPAD + q * HW;
    float v = 0.f;
    #pragma unroll
    for (int i = 0; i < 4; i++) {
        int n = lane + 32 * i;
        if (n < HW) {
            float x = cs[n] * (1.0f / 99.0f);
            x = (x >= 0.f) ? x : 0.2f * x;
            v += x * cw[n];
        }
    }
    #pragma unroll
    for (int o = 16; o; o >>= 1) v += __shfl_xor_sync(~0u, v, o);
    if (!lane) out[wid] = v + cb[0];
}

// ---------------- launch ----------------
extern "C" void kernel_launch(void* const* d_in, const int* in_sizes, int n_in,
                              void* d_out, int out_size) {
    const float* qf = (const float*)d_in[0];
    const float* sf = (const float*)d_in[1];
    const float* cw = (const float*)d_in[2];
    const float* cb = (const float*)d_in[3];
    float* out = (float*)d_out;

    __half *dS, *dQ;
    float *dMS, *dCS;
    cudaGetSymbolAddress((void**)&dS,  g_S16);
    cudaGetSymbolAddress((void**)&dQ,  g_Q16);
    cudaGetSymbolAddress((void**)&dMS, g_meanS);
    cudaGetSymbolAddress((void**)&dCS, g_colsum);

    {   // 1) support means
        int warps = T * WAY * C;
        means_s_kernel<<<(warps * 32 + 255) / 256, 256>>>(sf, dMS);
    }
    {   // 2) center+transpose S -> fp16 (coalesced)
        center_s_kernel<<<T * WS * (C / 64), 256>>>(sf, dMS, dS);
    }
    {   // 3) center(fused mean)+transpose Q -> fp16 (coalesced)
        center_q_kernel<<<T * WQ * (C / 64), 256>>>(qf, dQ);
    }
    {   // 4) zero padding rows
        int n = T * WAY * (MS - SHOT * HW) * (C / 2) + T * (NPAD - NQ) * (C / 2);
        pad_kernel<<<(n + 255) / 256, 256>>>(dS, dQ);
    }
    {   // 5) zero accumulator
        int n = T * WAY * NPAD;
        zero_cs_kernel<<<(n + 255) / 256, 256>>>(dCS);
    }
    {   // 6) fp16 HMMA GEMM + fused sum-of-squares  (6th launch -> ncu captures this)
        cudaFuncSetAttribute(gemm_hmma_kernel, cudaFuncAttributeMaxDynamicSharedMemorySize, SMEM_TOTAL);
        dim3 grid(NPAD / BN, MTOT / BM, T);   // (30, 20, 4)
        gemm_hmma_kernel<<<grid, 256, SMEM_TOTAL>>>(dS, dQ, dCS);
    }
    {   // 7) final score
        int warps = T * WQ * WAY;
        final_kernel<<<(warps * 32 + 255) / 256, 256>>>(dCS, cw, cb, out);
    }
}

// round 5
// speedup vs baseline: 4.0463x; 1.0523x over previous
#include <cuda_runtime.h>
#include <cuda_fp16.h>
#include <cstdint>
#include <cstddef>

// ---------------- problem constants ----------------
#define T     4
#define WQ    75
#define WAY   5
#define SHOT  5
#define WS    (WAY*SHOT)        // 25
#define C     640
#define HW    100
#define MS    512               // padded rows per way (500 real + 12 zero)
#define MTOT  (WAY*MS)          // 2560
#define NQ    (WQ*HW)           // 7500
#define NPAD  7680              // 30 * 256
#define BM    128
#define BN    256
#define BKH   64                // K halves per chunk => 128B smem rows
#define KT    (C/BKH)           // 10
#define STAGES 4

#define A_BYTES    (BM*128)     // 16384
#define B_BYTES    (BN*128)     // 32768
#define STAGE_BYTES (A_BYTES + B_BYTES)              // 49152
#define SMEM_TOTAL  (STAGES*STAGE_BYTES)             // 196608

#define SWZ(o) ((o) ^ (((o) >> 3) & 0x70))
#define WAITG(n) asm volatile("cp.async.wait_group %0;" :: "n"(n))

__device__ __forceinline__ uint32_t smem_u32(const void* p) {
    uint32_t a;
    asm("{ .reg .u64 t; cvta.to.shared.u64 t, %1; cvt.u32.u64 %0, t; }" : "=r"(a) : "l"(p));
    return a;
}

// ---------------- scratch (__device__ globals) ----------------
__device__ __align__(256) __half g_S16[(size_t)T * MTOT * C];   // 13.1 MB
__device__ __align__(256) __half g_Q16[(size_t)T * NPAD * C];   // 39.3 MB
__device__ float g_meanS[T * WAY * C];
__device__ __align__(16) float g_colsum[T * WAY * NPAD];

// ---------------- kernel 1: fused prep — support means + pad S/Q + zero colsum ----------------
#define MEAN_BLOCKS 1600        // 12800 warps, one per (t,way,c)
#define NS_PAD  (T * WAY * (MS - SHOT*HW) * (C/2))    // 76800 half2
#define NQ_PAD  (T * (NPAD - NQ) * (C/2))             // 230400 half2
#define PAD_BLOCKS ((NS_PAD + NQ_PAD) / 256)          // 1200
#define ZERO_BLOCKS ((T * WAY * NPAD) / 4 / 256)      // 150
__global__ void prep_kernel(const float* __restrict__ sf, float* __restrict__ ms,
                            __half* __restrict__ S, __half* __restrict__ Q,
                            float* __restrict__ cs) {
    int b = blockIdx.x;
    int tid = threadIdx.x;
    if (b < MEAN_BLOCKS) {
        int wid  = (b * 256 + tid) >> 5;
        int lane = tid & 31;
        int c   = wid % C;
        int way = (wid / C) % WAY;
        int t   = wid / (C * WAY);
        float v = 0.f;
        #pragma unroll
        for (int sh = 0; sh < SHOT; sh++) {
            const float* p = sf + ((size_t)((t * WAY + way) * SHOT + sh) * C + c) * HW;
            v += p[lane] + p[lane + 32] + p[lane + 64];
            if (lane < 4) v += p[lane + 96];
        }
        #pragma unroll
        for (int o = 16; o; o >>= 1) v += __shfl_xor_sync(~0u, v, o);
        if (!lane) ms[wid] = v * (1.0f / (SHOT * HW));
    } else if (b < MEAN_BLOCKS + PAD_BLOCKS) {
        int i = (b - MEAN_BLOCKS) * 256 + tid;
        if (i < NS_PAD) {
            int cp = i % (C / 2);
            int r  = (i / (C / 2)) % (MS - SHOT * HW);
            int wy = (i / ((C / 2) * (MS - SHOT * HW))) % WAY;
            int t  = i / ((C / 2) * (MS - SHOT * HW) * WAY);
            ((__half2*)S)[((size_t)t * MTOT + wy * MS + SHOT * HW + r) * (C / 2) + cp] =
                __floats2half2_rn(0.f, 0.f);
        } else {
            int j = i - NS_PAD;
            int cp = j % (C / 2);
            int r  = (j / (C / 2)) % (NPAD - NQ);
            int t  = j / ((C / 2) * (NPAD - NQ));
            ((__half2*)Q)[((size_t)t * NPAD + NQ + r) * (C / 2) + cp] =
                __floats2half2_rn(0.f, 0.f);
        }
    } else {
        int i = (b - MEAN_BLOCKS - PAD_BLOCKS) * 256 + tid;
        ((float4*)cs)[i] = make_float4(0.f, 0.f, 0.f, 0.f);
    }
}

// ---------------- kernel 2: coalesced center+transpose support -> fp16 K-major ----------------
__global__ void __launch_bounds__(256) center_s_kernel(const float* __restrict__ sf,
                                                       const float* __restrict__ ms,
                                                       __half* __restrict__ out) {
    __shared__ float tile[64 * 101];
    int b  = blockIdx.x;
    int cc = b % (C / 64);
    int ws = (b / (C / 64)) % WS;
    int t  = b / ((C / 64) * WS);
    int way = ws / SHOT, sh = ws % SHOT;
    int c0 = cc * 64;
    const float* src = sf + ((size_t)(t * WS + ws) * C + c0) * HW;
    int tid = threadIdx.x;
    #pragma unroll
    for (int i = 0; i < 25; i++) {
        int idx = tid + i * 256;
        tile[(idx / 100) * 101 + (idx % 100)] = src[idx];
    }
    __syncthreads();
    const float* mrow = ms + (t * WAY + way) * C + c0;
    __half2* dst = (__half2*)(out + ((size_t)t * MTOT + way * MS + sh * HW) * C + c0);
    for (int i = tid; i < 32 * HW; i += 256) {
        int n = i / 32, cp = i % 32;
        float v0 = tile[(cp * 2) * 101 + n] - mrow[cp * 2];
        float v1 = tile[(cp * 2 + 1) * 101 + n] - mrow[cp * 2 + 1];
        dst[(size_t)n * (C / 2) + cp] = __floats2half2_rn(v0, v1);
    }
}

// ---------------- kernel 3: coalesced center(fused mean)+transpose query -> fp16 ----------------
__global__ void __launch_bounds__(256) center_q_kernel(const float* __restrict__ qf,
                                                       __half* __restrict__ out) {
    __shared__ float tile[64 * 101];
    __shared__ float mean[64];
    int b  = blockIdx.x;
    int cc = b % (C / 64);
    int q  = (b / (C / 64)) % WQ;
    int t  = b / ((C / 64) * WQ);
    int c0 = cc * 64;
    const float* src = qf + ((size_t)(t * WQ + q) * C + c0) * HW;
    int tid = threadIdx.x, warp = tid >> 5, lane = tid & 31;
    #pragma unroll
    for (int i = 0; i < 25; i++) {
        int idx = tid + i * 256;
        tile[(idx / 100) * 101 + (idx % 100)] = src[idx];
    }
    __syncthreads();
    #pragma unroll
    for (int r = warp; r < 64; r += 8) {
        const float* row = &tile[r * 101];
        float v = row[lane] + row[lane + 32] + row[lane + 64];
        if (lane < 4) v += row[lane + 96];
        #pragma unroll
        for (int o = 16; o; o >>= 1) v += __shfl_xor_sync(~0u, v, o);
        if (!lane) mean[r] = v * (1.0f / HW);
    }
    __syncthreads();
    __half2* dst = (__half2*)(out + ((size_t)t * NPAD + q * HW) * C + c0);
    for (int i = tid; i < 32 * HW; i += 256) {
        int n = i / 32, cp = i % 32;
        float v0 = tile[(cp * 2) * 101 + n] - mean[cp * 2];
        float v1 = tile[(cp * 2 + 1) * 101 + n] - mean[cp * 2 + 1];
        dst[(size_t)n * (C / 2) + cp] = __floats2half2_rn(v0, v1);
    }
}

// ---------------- kernel 4: fp16 HMMA GEMM (128x256) + fused column sum-of-squares ----------------
// 4 stages, issue-ahead 2, ONE __syncthreads per K chunk.
__global__ void __launch_bounds__(256, 1) gemm_hmma_kernel(const __half* __restrict__ A,
                                                           const __half* __restrict__ B,
                                                           float* __restrict__ colsum) {
    extern __shared__ char smem[];
    const uint32_t sb = smem_u32(smem);

    const int tid  = threadIdx.x;
    const int warp = tid >> 5, lane = tid & 31;
    const int wm = warp & 1;
    const int wn = warp >> 1;
    const int gid = lane >> 2, tig = lane & 3;

    const int t  = blockIdx.z;
    const int m0 = blockIdx.y * BM;
    const int n0 = blockIdx.x * BN;
    const __half* Ap = A + ((size_t)t * MTOT + m0) * C;
    const __half* Bp = B + ((size_t)t * NPAD + n0) * C;

    const int arow = lane & 15;
    const int akof = (lane >> 4) * 16;
    const int brow = ((lane >> 4) << 3) | (lane & 7);
    const int bkof = ((lane >> 3) & 1) * 16;

    auto issue = [&](int kc) {
        const int s  = kc & (STAGES - 1);
        const int k0 = kc * BKH;
        const uint32_t sA = sb + s * STAGE_BYTES;
        const uint32_t sB = sA + A_BYTES;
        #pragma unroll
        for (int it = 0; it < 4; it++) {
            int i   = tid + it * 256;
            int row = i >> 3, ch = i & 7;
            uint32_t dst = sA + SWZ(row * 128 + ch * 16);
            const __half* src = Ap + (size_t)row * C + k0 + ch * 8;
            asm volatile("cp.async.cg.shared.global [%0], [%1], 16;" :: "r"(dst), "l"(src));
        }
        #pragma unroll
        for (int it = 0; it < 8; it++) {
            int i   = tid + it * 256;
            int row = i >> 3, ch = i & 7;
            uint32_t dst = sB + SWZ(row * 128 + ch * 16);
            const __half* src = Bp + (size_t)row * C + k0 + ch * 8;
            asm volatile("cp.async.cg.shared.global [%0], [%1], 16;" :: "r"(dst), "l"(src));
        }
        asm volatile("cp.async.commit_group;");
    };

    float acc[4][8][4];
    #pragma unroll
    for (int mi = 0; mi < 4; mi++)
        #pragma unroll
        for (int ni = 0; ni < 8; ni++)
            #pragma unroll
            for (int r = 0; r < 4; r++) acc[mi][ni][r] = 0.f;

    issue(0); issue(1);

    for (int kc = 0; kc < KT; kc++) {
        if (kc + 2 < KT)      { issue(kc + 2); WAITG(2); }
        else if (kc + 1 < KT) { WAITG(1); }
        else                  { WAITG(0); }
        __syncthreads();      // single barrier: data ready + stage-reuse fence

        const uint32_t sA = sb + (kc & (STAGES - 1)) * STAGE_BYTES;
        const uint32_t sB = sA + A_BYTES;

        #pragma unroll
        for (int ks = 0; ks < 4; ks++) {
            const int kb = ks * 32;
            uint32_t a[4][4], b[8][2];
            #pragma unroll
            for (int mi = 0; mi < 4; mi++) {
                uint32_t addr = sA + SWZ((wm * 64 + mi * 16 + arow) * 128 + kb + akof);
                asm volatile("ldmatrix.sync.aligned.m8n8.x4.shared.b16 {%0,%1,%2,%3}, [%4];"
                             : "=r"(a[mi][0]), "=r"(a[mi][1]), "=r"(a[mi][2]), "=r"(a[mi][3])
                             : "r"(addr));
            }
            #pragma unroll
            for (int nj = 0; nj < 4; nj++) {
                uint32_t addr = sB + SWZ((wn * 64 + nj * 16 + brow) * 128 + kb + bkof);
                asm volatile("ldmatrix.sync.aligned.m8n8.x4.shared.b16 {%0,%1,%2,%3}, [%4];"
                             : "=r"(b[nj*2][0]), "=r"(b[nj*2][1]),
                               "=r"(b[nj*2+1][0]), "=r"(b[nj*2+1][1])
                             : "r"(addr));
            }
            #pragma unroll
            for (int mi = 0; mi < 4; mi++)
                #pragma unroll
                for (int ni = 0; ni < 8; ni++) {
                    asm volatile(
                        "mma.sync.aligned.m16n8k16.row.col.f32.f16.f16.f32 "
                        "{%0,%1,%2,%3}, {%4,%5,%6,%7}, {%8,%9}, {%0,%1,%2,%3};"
                        : "+f"(acc[mi][ni][0]), "+f"(acc[mi][ni][1]),
                          "+f"(acc[mi][ni][2]), "+f"(acc[mi][ni][3])
                        : "r"(a[mi][0]), "r"(a[mi][1]), "r"(a[mi][2]), "r"(a[mi][3]),
                          "r"(b[ni][0]), "r"(b[ni][1]));
                }
        }
    }

    const int way = m0 / MS;
    float* cs = colsum + ((size_t)t * WAY + way) * NPAD + n0;
    #pragma unroll
    for (int ni = 0; ni < 8; ni++) {
        float v0 = 0.f, v1 = 0.f;
        #pragma unroll
        for (int mi = 0; mi < 4; mi++) {
            v0 += acc[mi][ni][0] * acc[mi][ni][0] + acc[mi][ni][2] * acc[mi][ni][2];
            v1 += acc[mi][ni][1] * acc[mi][ni][1] + acc[mi][ni][3] * acc[mi][ni][3];
        }
        #pragma unroll
        for (int o = 4; o < 32; o <<= 1) {
            v0 += __shfl_xor_sync(~0u, v0, o);
            v1 += __shfl_xor_sync(~0u, v1, o);
        }
        if (gid == 0) {
            int col = wn * 64 + ni * 8 + tig * 2;
            atomicAdd(&cs[col], v0);
            atomicAdd(&cs[col + 1], v1);
        }
    }
}

// ---------------- kernel 5: /99, LeakyReLU(0.2), conv1d(k=stride=100), +bias ----------------
__global__ void final_kernel(const float* __restrict__ colsum, const float* __restrict__ cw,
                             const float* __restrict__ cb, float* __restrict__ out) {
    int wid  = (blockIdx.x * blockDim.x + threadIdx.x) >> 5;
    int lane = threadIdx.x & 31;
    if (wid >= T * WQ * WAY) return;
    int w = wid % WAY;
    int q = (wid / WAY) % WQ;
    int t = wid / (WAY * WQ);
    const float* cs = colsum + ((size_t)t * WAY + w) * NPAD + q * HW;
    float v = 0.f;
    #pragma unroll
    for (int i = 0; i < 4; i++) {
        int n = lane + 32 * i;
        if (n < HW) {
            float x = cs[n] * (1.0f / 99.0f);
            x = (x >= 0.f) ? x : 0.2f * x;
            v += x * cw[n];
        }
    }
    #pragma unroll
    for (int o = 16; o; o >>= 1) v += __shfl_xor_sync(~0u, v, o);
    if (!lane) out[wid] = v + cb[0];
}

// ---------------- launch ----------------
extern "C" void kernel_launch(void* const* d_in, const int* in_sizes, int n_in,
                              void* d_out, int out_size) {
    const float* qf = (const float*)d_in[0];
    const float* sf = (const float*)d_in[1];
    const float* cw = (const float*)d_in[2];
    const float* cb = (const float*)d_in[3];
    float* out = (float*)d_out;

    __half *dS, *dQ;
    float *dMS, *dCS;
    cudaGetSymbolAddress((void**)&dS,  g_S16);
    cudaGetSymbolAddress((void**)&dQ,  g_Q16);
    cudaGetSymbolAddress((void**)&dMS, g_meanS);
    cudaGetSymbolAddress((void**)&dCS, g_colsum);

    // 1) fused prep: support means + pads + zero colsum
    prep_kernel<<<MEAN_BLOCKS + PAD_BLOCKS + ZERO_BLOCKS, 256>>>(sf, dMS, dS, dQ, dCS);
    // 2) center+transpose S -> fp16
    center_s_kernel<<<T * WS * (C / 64), 256>>>(sf, dMS, dS);
    // 3) center(fused mean)+transpose Q -> fp16
    center_q_kernel<<<T * WQ * (C / 64), 256>>>(qf, dQ);
    // 4) GEMM + fused sum-of-squares   (4th launch -> ncu capture slot)
    cudaFuncSetAttribute(gemm_hmma_kernel, cudaFuncAttributeMaxDynamicSharedMemorySize, SMEM_TOTAL);
    dim3 grid(NPAD / BN, MTOT / BM, T);   // (30, 20, 4)
    gemm_hmma_kernel<<<grid, 256, SMEM_TOTAL>>>(dS, dQ, dCS);
    // 5) final score
    int warps = T * WQ * WAY;
    final_kernel<<<(warps * 32 + 255) / 256, 256>>>(dCS, cw, cb, out);
}

// round 6
// speedup vs baseline: 4.2914x; 1.0606x over previous
#include <cuda_runtime.h>
#include <cuda_fp16.h>
#include <cstdint>
#include <cstddef>

// ---------------- problem constants ----------------
#define T     4
#define WQ    75
#define WAY   5
#define SHOT  5
#define WS    (WAY*SHOT)        // 25
#define C     640
#define HW    100
#define MS    512               // padded rows per way (500 real + 12 zero)
#define MTOT  (WAY*MS)          // 2560
#define NQ    (WQ*HW)           // 7500
#define NPAD  7680              // 60 * 128
#define BM    128
#define BN    128
#define BKH   64                // K halves per chunk => 128B smem rows
#define KT    (C/BKH)           // 10
#define STAGES 3

#define A_BYTES    (BM*128)     // 16384
#define B_BYTES    (BN*128)     // 16384
#define STAGE_BYTES (A_BYTES + B_BYTES)              // 32768
#define SMEM_TOTAL  (STAGES*STAGE_BYTES)             // 98304

#define SWZ(o) ((o) ^ (((o) >> 3) & 0x70))
#define WAITG(n) asm volatile("cp.async.wait_group %0;" :: "n"(n))

__device__ __forceinline__ uint32_t smem_u32(const void* p) {
    uint32_t a;
    asm("{ .reg .u64 t; cvta.to.shared.u64 t, %1; cvt.u32.u64 %0, t; }" : "=r"(a) : "l"(p));
    return a;
}

// ---------------- scratch (__device__ globals) ----------------
__device__ __align__(256) __half g_S16[(size_t)T * MTOT * C];   // 13.1 MB
__device__ __align__(256) __half g_Q16[(size_t)T * NPAD * C];   // 39.3 MB
__device__ float g_meanS[T * WAY * C];
__device__ __align__(16) float g_colsum[T * WAY * NPAD];

// ---------------- kernel 1: fused prep — support means + pad S/Q + zero colsum ----------------
#define MEAN_BLOCKS 1600        // 12800 warps, one per (t,way,c)
#define NS_PAD  (T * WAY * (MS - SHOT*HW) * (C/2))    // 76800 half2
#define NQ_PAD  (T * (NPAD - NQ) * (C/2))             // 230400 half2
#define PAD_BLOCKS ((NS_PAD + NQ_PAD) / 256)          // 1200
#define ZERO_BLOCKS ((T * WAY * NPAD) / 4 / 256)      // 150
__global__ void prep_kernel(const float* __restrict__ sf, float* __restrict__ ms,
                            __half* __restrict__ S, __half* __restrict__ Q,
                            float* __restrict__ cs) {
    int b = blockIdx.x;
    int tid = threadIdx.x;
    if (b < MEAN_BLOCKS) {
        int wid  = (b * 256 + tid) >> 5;
        int lane = tid & 31;
        int c   = wid % C;
        int way = (wid / C) % WAY;
        int t   = wid / (C * WAY);
        float v = 0.f;
        #pragma unroll
        for (int sh = 0; sh < SHOT; sh++) {
            const float* p = sf + ((size_t)((t * WAY + way) * SHOT + sh) * C + c) * HW;
            v += p[lane] + p[lane + 32] + p[lane + 64];
            if (lane < 4) v += p[lane + 96];
        }
        #pragma unroll
        for (int o = 16; o; o >>= 1) v += __shfl_xor_sync(~0u, v, o);
        if (!lane) ms[wid] = v * (1.0f / (SHOT * HW));
    } else if (b < MEAN_BLOCKS + PAD_BLOCKS) {
        int i = (b - MEAN_BLOCKS) * 256 + tid;
        if (i < NS_PAD) {
            int cp = i % (C / 2);
            int r  = (i / (C / 2)) % (MS - SHOT * HW);
            int wy = (i / ((C / 2) * (MS - SHOT * HW))) % WAY;
            int t  = i / ((C / 2) * (MS - SHOT * HW) * WAY);
            ((__half2*)S)[((size_t)t * MTOT + wy * MS + SHOT * HW + r) * (C / 2) + cp] =
                __floats2half2_rn(0.f, 0.f);
        } else {
            int j = i - NS_PAD;
            int cp = j % (C / 2);
            int r  = (j / (C / 2)) % (NPAD - NQ);
            int t  = j / ((C / 2) * (NPAD - NQ));
            ((__half2*)Q)[((size_t)t * NPAD + NQ + r) * (C / 2) + cp] =
                __floats2half2_rn(0.f, 0.f);
        }
    } else {
        int i = (b - MEAN_BLOCKS - PAD_BLOCKS) * 256 + tid;
        ((float4*)cs)[i] = make_float4(0.f, 0.f, 0.f, 0.f);
    }
}

// ---------------- kernel 2: coalesced center+transpose support -> fp16 K-major ----------------
__global__ void __launch_bounds__(256) center_s_kernel(const float* __restrict__ sf,
                                                       const float* __restrict__ ms,
                                                       __half* __restrict__ out) {
    __shared__ float tile[64 * 101];
    int b  = blockIdx.x;
    int cc = b % (C / 64);
    int ws = (b / (C / 64)) % WS;
    int t  = b / ((C / 64) * WS);
    int way = ws / SHOT, sh = ws % SHOT;
    int c0 = cc * 64;
    const float* src = sf + ((size_t)(t * WS + ws) * C + c0) * HW;
    int tid = threadIdx.x;
    #pragma unroll
    for (int i = 0; i < 25; i++) {
        int idx = tid + i * 256;
        tile[(idx / 100) * 101 + (idx % 100)] = src[idx];
    }
    __syncthreads();
    const float* mrow = ms + (t * WAY + way) * C + c0;
    __half2* dst = (__half2*)(out + ((size_t)t * MTOT + way * MS + sh * HW) * C + c0);
    for (int i = tid; i < 32 * HW; i += 256) {
        int n = i / 32, cp = i % 32;
        float v0 = tile[(cp * 2) * 101 + n] - mrow[cp * 2];
        float v1 = tile[(cp * 2 + 1) * 101 + n] - mrow[cp * 2 + 1];
        dst[(size_t)n * (C / 2) + cp] = __floats2half2_rn(v0, v1);
    }
}

// ---------------- kernel 3: coalesced center(fused mean)+transpose query -> fp16 ----------------
__global__ void __launch_bounds__(256) center_q_kernel(const float* __restrict__ qf,
                                                       __half* __restrict__ out) {
    __shared__ float tile[64 * 101];
    __shared__ float mean[64];
    int b  = blockIdx.x;
    int cc = b % (C / 64);
    int q  = (b / (C / 64)) % WQ;
    int t  = b / ((C / 64) * WQ);
    int c0 = cc * 64;
    const float* src = qf + ((size_t)(t * WQ + q) * C + c0) * HW;
    int tid = threadIdx.x, warp = tid >> 5, lane = tid & 31;
    #pragma unroll
    for (int i = 0; i < 25; i++) {
        int idx = tid + i * 256;
        tile[(idx / 100) * 101 + (idx % 100)] = src[idx];
    }
    __syncthreads();
    #pragma unroll
    for (int r = warp; r < 64; r += 8) {
        const float* row = &tile[r * 101];
        float v = row[lane] + row[lane + 32] + row[lane + 64];
        if (lane < 4) v += row[lane + 96];
        #pragma unroll
        for (int o = 16; o; o >>= 1) v += __shfl_xor_sync(~0u, v, o);
        if (!lane) mean[r] = v * (1.0f / HW);
    }
    __syncthreads();
    __half2* dst = (__half2*)(out + ((size_t)t * NPAD + q * HW) * C + c0);
    for (int i = tid; i < 32 * HW; i += 256) {
        int n = i / 32, cp = i % 32;
        float v0 = tile[(cp * 2) * 101 + n] - mean[cp * 2];
        float v1 = tile[(cp * 2 + 1) * 101 + n] - mean[cp * 2 + 1];
        dst[(size_t)n * (C / 2) + cp] = __floats2half2_rn(v0, v1);
    }
}

// ---------------- kernel 4: fp16 HMMA GEMM (128x128) + fused column sum-of-squares ----------------
// 2 CTAs/SM (96KB smem, <=128 regs). 8 warps 2(M)x4(N), warp tile 64x32.
// 3 stages; order per chunk: WAITG -> syncthreads -> issue(kc+2) -> compute.
__global__ void __launch_bounds__(256, 2) gemm_hmma_kernel(const __half* __restrict__ A,
                                                           const __half* __restrict__ B,
                                                           float* __restrict__ colsum) {
    extern __shared__ char smem[];
    const uint32_t sb = smem_u32(smem);

    const int tid  = threadIdx.x;
    const int warp = tid >> 5, lane = tid & 31;
    const int wm = warp & 1;          // 0..1 : 64-row half (M)
    const int wn = warp >> 1;         // 0..3 : 32-col quarter (N)
    const int gid = lane >> 2, tig = lane & 3;

    const int t  = blockIdx.z;
    const int m0 = blockIdx.y * BM;
    const int n0 = blockIdx.x * BN;
    const __half* Ap = A + ((size_t)t * MTOT + m0) * C;
    const __half* Bp = B + ((size_t)t * NPAD + n0) * C;

    const int arow = lane & 15;
    const int akof = (lane >> 4) * 16;
    const int brow = ((lane >> 4) << 3) | (lane & 7);
    const int bkof = ((lane >> 3) & 1) * 16;

    auto issue = [&](int kc) {
        const int s  = kc % STAGES;
        const int k0 = kc * BKH;
        const uint32_t sA = sb + s * STAGE_BYTES;
        const uint32_t sB = sA + A_BYTES;
        #pragma unroll
        for (int it = 0; it < 4; it++) {               // A: 1024 x 16B
            int i   = tid + it * 256;
            int row = i >> 3, ch = i & 7;
            uint32_t dst = sA + SWZ(row * 128 + ch * 16);
            const __half* src = Ap + (size_t)row * C + k0 + ch * 8;
            asm volatile("cp.async.cg.shared.global [%0], [%1], 16;" :: "r"(dst), "l"(src));
        }
        #pragma unroll
        for (int it = 0; it < 4; it++) {               // B: 1024 x 16B
            int i   = tid + it * 256;
            int row = i >> 3, ch = i & 7;
            uint32_t dst = sB + SWZ(row * 128 + ch * 16);
            const __half* src = Bp + (size_t)row * C + k0 + ch * 8;
            asm volatile("cp.async.cg.shared.global [%0], [%1], 16;" :: "r"(dst), "l"(src));
        }
        asm volatile("cp.async.commit_group;");
    };

    float acc[4][4][4];
    #pragma unroll
    for (int mi = 0; mi < 4; mi++)
        #pragma unroll
        for (int ni = 0; ni < 4; ni++)
            #pragma unroll
            for (int r = 0; r < 4; r++) acc[mi][ni][r] = 0.f;

    issue(0); issue(1);

    for (int kc = 0; kc < KT; kc++) {
        if (kc < KT - 1) { WAITG(1); }   // stage kc complete (1 newer group may pend)
        else             { WAITG(0); }
        __syncthreads();                 // data visible + all warps done reading stage (kc-1)%3
        if (kc + 2 < KT) issue(kc + 2);  // writes stage (kc-1)%3 — safe after the sync

        const uint32_t sA = sb + (kc % STAGES) * STAGE_BYTES;
        const uint32_t sB = sA + A_BYTES;

        #pragma unroll
        for (int ks = 0; ks < 4; ks++) {
            const int kb = ks * 32;
            uint32_t a[4][4], b[4][2];
            #pragma unroll
            for (int mi = 0; mi < 4; mi++) {
                uint32_t addr = sA + SWZ((wm * 64 + mi * 16 + arow) * 128 + kb + akof);
                asm volatile("ldmatrix.sync.aligned.m8n8.x4.shared.b16 {%0,%1,%2,%3}, [%4];"
                             : "=r"(a[mi][0]), "=r"(a[mi][1]), "=r"(a[mi][2]), "=r"(a[mi][3])
                             : "r"(addr));
            }
            #pragma unroll
            for (int nj = 0; nj < 2; nj++) {           // 32 cols = 2 x (16-row x4)
                uint32_t addr = sB + SWZ((wn * 32 + nj * 16 + brow) * 128 + kb + bkof);
                asm volatile("ldmatrix.sync.aligned.m8n8.x4.shared.b16 {%0,%1,%2,%3}, [%4];"
                             : "=r"(b[nj*2][0]), "=r"(b[nj*2][1]),
                               "=r"(b[nj*2+1][0]), "=r"(b[nj*2+1][1])
                             : "r"(addr));
            }
            #pragma unroll
            for (int mi = 0; mi < 4; mi++)
                #pragma unroll
                for (int ni = 0; ni < 4; ni++) {
                    asm volatile(
                        "mma.sync.aligned.m16n8k16.row.col.f32.f16.f16.f32 "
                        "{%0,%1,%2,%3}, {%4,%5,%6,%7}, {%8,%9}, {%0,%1,%2,%3};"
                        : "+f"(acc[mi][ni][0]), "+f"(acc[mi][ni][1]),
                          "+f"(acc[mi][ni][2]), "+f"(acc[mi][ni][3])
                        : "r"(a[mi][0]), "r"(a[mi][1]), "r"(a[mi][2]), "r"(a[mi][3]),
                          "r"(b[ni][0]), "r"(b[ni][1]));
                }
        }
    }

    // -------- fused epilogue: column sum of squares over this CTA's 128 rows --------
    const int way = m0 / MS;
    float* cs = colsum + ((size_t)t * WAY + way) * NPAD + n0;
    #pragma unroll
    for (int ni = 0; ni < 4; ni++) {
        float v0 = 0.f, v1 = 0.f;
        #pragma unroll
        for (int mi = 0; mi < 4; mi++) {
            v0 += acc[mi][ni][0] * acc[mi][ni][0] + acc[mi][ni][2] * acc[mi][ni][2];
            v1 += acc[mi][ni][1] * acc[mi][ni][1] + acc[mi][ni][3] * acc[mi][ni][3];
        }
        #pragma unroll
        for (int o = 4; o < 32; o <<= 1) {
            v0 += __shfl_xor_sync(~0u, v0, o);
            v1 += __shfl_xor_sync(~0u, v1, o);
        }
        if (gid == 0) {
            int col = wn * 32 + ni * 8 + tig * 2;
            atomicAdd(&cs[col], v0);
            atomicAdd(&cs[col + 1], v1);
        }
    }
}

// ---------------- kernel 5: /99, LeakyReLU(0.2), conv1d(k=stride=100), +bias ----------------
__global__ void final_kernel(const float* __restrict__ colsum, const float* __restrict__ cw,
                             const float* __restrict__ cb, float* __restrict__ out) {
    int wid  = (blockIdx.x * blockDim.x + threadIdx.x) >> 5;
    int lane = threadIdx.x & 31;
    if (wid >= T * WQ * WAY) return;
    int w = wid % WAY;
    int q = (wid / WAY) % WQ;
    int t = wid / (WAY * WQ);
    const float* cs = colsum + ((size_t)t * WAY + w) * NPAD + q * HW;
    float v = 0.f;
    #pragma unroll
    for (int i = 0; i < 4; i++) {
        int n = lane + 32 * i;
        if (n < HW) {
            float x = cs[n] * (1.0f / 99.0f);
            x = (x >= 0.f) ? x : 0.2f * x;
            v += x * cw[n];
        }
    }
    #pragma unroll
    for (int o = 16; o; o >>= 1) v += __shfl_xor_sync(~0u, v, o);
    if (!lane) out[wid] = v + cb[0];
}

// ---------------- launch ----------------
extern "C" void kernel_launch(void* const* d_in, const int* in_sizes, int n_in,
                              void* d_out, int out_size) {
    const float* qf = (const float*)d_in[0];
    const float* sf = (const float*)d_in[1];
    const float* cw = (const float*)d_in[2];
    const float* cb = (const float*)d_in[3];
    float* out = (float*)d_out;

    __half *dS, *dQ;
    float *dMS, *dCS;
    cudaGetSymbolAddress((void**)&dS,  g_S16);
    cudaGetSymbolAddress((void**)&dQ,  g_Q16);
    cudaGetSymbolAddress((void**)&dMS, g_meanS);
    cudaGetSymbolAddress((void**)&dCS, g_colsum);

    // 1) fused prep: support means + pads + zero colsum
    prep_kernel<<<MEAN_BLOCKS + PAD_BLOCKS + ZERO_BLOCKS, 256>>>(sf, dMS, dS, dQ, dCS);
    // 2) center+transpose S -> fp16
    center_s_kernel<<<T * WS * (C / 64), 256>>>(sf, dMS, dS);
    // 3) center(fused mean)+transpose Q -> fp16
    center_q_kernel<<<T * WQ * (C / 64), 256>>>(qf, dQ);
    // 4) GEMM + fused sum-of-squares   (4th launch -> ncu capture slot)
    cudaFuncSetAttribute(gemm_hmma_kernel, cudaFuncAttributeMaxDynamicSharedMemorySize, SMEM_TOTAL);
    dim3 grid(NPAD / BN, MTOT / BM, T);   // (60, 20, 4)
    gemm_hmma_kernel<<<grid, 256, SMEM_TOTAL>>>(dS, dQ, dCS);
    // 5) final score
    int warps = T * WQ * WAY;
    final_kernel<<<(warps * 32 + 255) / 256, 256>>>(dCS, cw, cb, out);
}

// round 7
// speedup vs baseline: 4.3026x; 1.0026x over previous
#include <cuda_runtime.h>
#include <cuda_fp16.h>
#include <cstdint>
#include <cstddef>

// ---------------- problem constants ----------------
#define T     4
#define WQ    75
#define WAY   5
#define SHOT  5
#define WS    (WAY*SHOT)        // 25
#define C     640
#define HW    100
#define MS    512               // padded rows per way (500 real + 12 zero)
#define MTOT  (WAY*MS)          // 2560
#define NQ    (WQ*HW)           // 7500
#define NPAD  7680              // 60 * 128
#define BM    128
#define BN    128
#define BKH   64                // K halves per chunk => 128B smem rows
#define KT    (C/BKH)           // 10
#define STAGES 3

#define A_BYTES    (BM*128)     // 16384
#define B_BYTES    (BN*128)     // 16384
#define STAGE_BYTES (A_BYTES + B_BYTES)              // 32768
#define SMEM_TOTAL  (STAGES*STAGE_BYTES)             // 98304

#define SWZ(o) ((o) ^ (((o) >> 3) & 0x70))
#define WAITG(n) asm volatile("cp.async.wait_group %0;" :: "n"(n))

__device__ __forceinline__ uint32_t smem_u32(const void* p) {
    uint32_t a;
    asm("{ .reg .u64 t; cvta.to.shared.u64 t, %1; cvt.u32.u64 %0, t; }" : "=r"(a) : "l"(p));
    return a;
}

// ---------------- scratch (__device__ globals) ----------------
__device__ __align__(256) __half g_S16[(size_t)T * MTOT * C];   // 13.1 MB
__device__ __align__(256) __half g_Q16[(size_t)T * NPAD * C];   // 39.3 MB
__device__ float g_meanS[T * WAY * C];
__device__ __align__(16) float g_colsum[T * WAY * NPAD];

// ---------------- kernel 1: fused prep — support means + pad S/Q + zero colsum ----------------
#define MEAN_BLOCKS 1600        // 12800 warps, one per (t,way,c)
#define NS_PAD  (T * WAY * (MS - SHOT*HW) * (C/2))    // 76800 half2
#define NQ_PAD  (T * (NPAD - NQ) * (C/2))             // 230400 half2
#define PAD_BLOCKS ((NS_PAD + NQ_PAD) / 256)          // 1200
#define ZERO_BLOCKS ((T * WAY * NPAD) / 4 / 256)      // 150
__global__ void prep_kernel(const float* __restrict__ sf, float* __restrict__ ms,
                            __half* __restrict__ S, __half* __restrict__ Q,
                            float* __restrict__ cs) {
    int b = blockIdx.x;
    int tid = threadIdx.x;
    if (b < MEAN_BLOCKS) {
        int wid  = (b * 256 + tid) >> 5;
        int lane = tid & 31;
        int c   = wid % C;
        int way = (wid / C) % WAY;
        int t   = wid / (C * WAY);
        float v = 0.f;
        #pragma unroll
        for (int sh = 0; sh < SHOT; sh++) {
            const float* p = sf + ((size_t)((t * WAY + way) * SHOT + sh) * C + c) * HW;
            v += p[lane] + p[lane + 32] + p[lane + 64];
            if (lane < 4) v += p[lane + 96];
        }
        #pragma unroll
        for (int o = 16; o; o >>= 1) v += __shfl_xor_sync(~0u, v, o);
        if (!lane) ms[wid] = v * (1.0f / (SHOT * HW));
    } else if (b < MEAN_BLOCKS + PAD_BLOCKS) {
        int i = (b - MEAN_BLOCKS) * 256 + tid;
        if (i < NS_PAD) {
            int cp = i % (C / 2);
            int r  = (i / (C / 2)) % (MS - SHOT * HW);
            int wy = (i / ((C / 2) * (MS - SHOT * HW))) % WAY;
            int t  = i / ((C / 2) * (MS - SHOT * HW) * WAY);
            ((__half2*)S)[((size_t)t * MTOT + wy * MS + SHOT * HW + r) * (C / 2) + cp] =
                __floats2half2_rn(0.f, 0.f);
        } else {
            int j = i - NS_PAD;
            int cp = j % (C / 2);
            int r  = (j / (C / 2)) % (NPAD - NQ);
            int t  = j / ((C / 2) * (NPAD - NQ));
            ((__half2*)Q)[((size_t)t * NPAD + NQ + r) * (C / 2) + cp] =
                __floats2half2_rn(0.f, 0.f);
        }
    } else {
        int i = (b - MEAN_BLOCKS - PAD_BLOCKS) * 256 + tid;
        ((float4*)cs)[i] = make_float4(0.f, 0.f, 0.f, 0.f);
    }
}

// ---------------- kernel 2: coalesced center+transpose support -> fp16 K-major ----------------
__global__ void __launch_bounds__(256) center_s_kernel(const float* __restrict__ sf,
                                                       const float* __restrict__ ms,
                                                       __half* __restrict__ out) {
    __shared__ float tile[64 * 101];
    int b  = blockIdx.x;
    int cc = b % (C / 64);
    int ws = (b / (C / 64)) % WS;
    int t  = b / ((C / 64) * WS);
    int way = ws / SHOT, sh = ws % SHOT;
    int c0 = cc * 64;
    const float* src = sf + ((size_t)(t * WS + ws) * C + c0) * HW;
    int tid = threadIdx.x;
    #pragma unroll
    for (int i = 0; i < 25; i++) {
        int idx = tid + i * 256;
        tile[(idx / 100) * 101 + (idx % 100)] = src[idx];
    }
    __syncthreads();
    const float* mrow = ms + (t * WAY + way) * C + c0;
    __half2* dst = (__half2*)(out + ((size_t)t * MTOT + way * MS + sh * HW) * C + c0);
    for (int i = tid; i < 32 * HW; i += 256) {
        int n = i / 32, cp = i % 32;
        float v0 = tile[(cp * 2) * 101 + n] - mrow[cp * 2];
        float v1 = tile[(cp * 2 + 1) * 101 + n] - mrow[cp * 2 + 1];
        dst[(size_t)n * (C / 2) + cp] = __floats2half2_rn(v0, v1);
    }
}

// ---------------- kernel 3: coalesced center(fused mean)+transpose query -> fp16 ----------------
__global__ void __launch_bounds__(256) center_q_kernel(const float* __restrict__ qf,
                                                       __half* __restrict__ out) {
    __shared__ float tile[64 * 101];
    __shared__ float mean[64];
    int b  = blockIdx.x;
    int cc = b % (C / 64);
    int q  = (b / (C / 64)) % WQ;
    int t  = b / ((C / 64) * WQ);
    int c0 = cc * 64;
    const float* src = qf + ((size_t)(t * WQ + q) * C + c0) * HW;
    int tid = threadIdx.x, warp = tid >> 5, lane = tid & 31;
    #pragma unroll
    for (int i = 0; i < 25; i++) {
        int idx = tid + i * 256;
        tile[(idx / 100) * 101 + (idx % 100)] = src[idx];
    }
    __syncthreads();
    #pragma unroll
    for (int r = warp; r < 64; r += 8) {
        const float* row = &tile[r * 101];
        float v = row[lane] + row[lane + 32] + row[lane + 64];
        if (lane < 4) v += row[lane + 96];
        #pragma unroll
        for (int o = 16; o; o >>= 1) v += __shfl_xor_sync(~0u, v, o);
        if (!lane) mean[r] = v * (1.0f / HW);
    }
    __syncthreads();
    __half2* dst = (__half2*)(out + ((size_t)t * NPAD + q * HW) * C + c0);
    for (int i = tid; i < 32 * HW; i += 256) {
        int n = i / 32, cp = i % 32;
        float v0 = tile[(cp * 2) * 101 + n] - mean[cp * 2];
        float v1 = tile[(cp * 2 + 1) * 101 + n] - mean[cp * 2 + 1];
        dst[(size_t)n * (C / 2) + cp] = __floats2half2_rn(v0, v1);
    }
}

// ---------------- kernel 4: fp16 HMMA GEMM (128x128) + fused column sum-of-squares ----------------
// 128 threads (4 warps, 2x2), warp tile 64x64 -> 1.5x less LDSM traffic than 64x32.
// 2 CTAs/SM (96KB smem, <=256 regs). 3 stages: WAITG -> sync -> issue(kc+2) -> compute.
__global__ void __launch_bounds__(128, 2) gemm_hmma_kernel(const __half* __restrict__ A,
                                                           const __half* __restrict__ B,
                                                           float* __restrict__ colsum) {
    extern __shared__ char smem[];
    const uint32_t sb = smem_u32(smem);

    const int tid  = threadIdx.x;
    const int warp = tid >> 5, lane = tid & 31;
    const int wm = warp & 1;          // 0..1 : 64-row half (M)
    const int wn = warp >> 1;         // 0..1 : 64-col half (N)
    const int gid = lane >> 2, tig = lane & 3;

    const int t  = blockIdx.z;
    const int m0 = blockIdx.y * BM;
    const int n0 = blockIdx.x * BN;
    const __half* Ap = A + ((size_t)t * MTOT + m0) * C;
    const __half* Bp = B + ((size_t)t * NPAD + n0) * C;

    const int arow = lane & 15;
    const int akof = (lane >> 4) * 16;
    const int brow = ((lane >> 4) << 3) | (lane & 7);
    const int bkof = ((lane >> 3) & 1) * 16;

    auto issue = [&](int kc) {
        const int s  = kc % STAGES;
        const int k0 = kc * BKH;
        const uint32_t sA = sb + s * STAGE_BYTES;
        const uint32_t sB = sA + A_BYTES;
        #pragma unroll
        for (int it = 0; it < 8; it++) {               // A: 1024 x 16B
            int i   = tid + it * 128;
            int row = i >> 3, ch = i & 7;
            uint32_t dst = sA + SWZ(row * 128 + ch * 16);
            const __half* src = Ap + (size_t)row * C + k0 + ch * 8;
            asm volatile("cp.async.cg.shared.global [%0], [%1], 16;" :: "r"(dst), "l"(src));
        }
        #pragma unroll
        for (int it = 0; it < 8; it++) {               // B: 1024 x 16B
            int i   = tid + it * 128;
            int row = i >> 3, ch = i & 7;
            uint32_t dst = sB + SWZ(row * 128 + ch * 16);
            const __half* src = Bp + (size_t)row * C + k0 + ch * 8;
            asm volatile("cp.async.cg.shared.global [%0], [%1], 16;" :: "r"(dst), "l"(src));
        }
        asm volatile("cp.async.commit_group;");
    };

    float acc[4][8][4];
    #pragma unroll
    for (int mi = 0; mi < 4; mi++)
        #pragma unroll
        for (int ni = 0; ni < 8; ni++)
            #pragma unroll
            for (int r = 0; r < 4; r++) acc[mi][ni][r] = 0.f;

    issue(0); issue(1);

    for (int kc = 0; kc < KT; kc++) {
        if (kc < KT - 1) { WAITG(1); }   // stage kc complete (1 newer group may pend)
        else             { WAITG(0); }
        __syncthreads();                 // data visible + all warps done reading stage (kc-1)%3
        if (kc + 2 < KT) issue(kc + 2);  // writes stage (kc-1)%3 — safe after the sync

        const uint32_t sA = sb + (kc % STAGES) * STAGE_BYTES;
        const uint32_t sB = sA + A_BYTES;

        #pragma unroll
        for (int ks = 0; ks < 4; ks++) {
            const int kb = ks * 32;
            uint32_t a[4][4], b[8][2];
            #pragma unroll
            for (int mi = 0; mi < 4; mi++) {
                uint32_t addr = sA + SWZ((wm * 64 + mi * 16 + arow) * 128 + kb + akof);
                asm volatile("ldmatrix.sync.aligned.m8n8.x4.shared.b16 {%0,%1,%2,%3}, [%4];"
                             : "=r"(a[mi][0]), "=r"(a[mi][1]), "=r"(a[mi][2]), "=r"(a[mi][3])
                             : "r"(addr));
            }
            #pragma unroll
            for (int nj = 0; nj < 4; nj++) {           // 64 cols = 4 x (16-row x4)
                uint32_t addr = sB + SWZ((wn * 64 + nj * 16 + brow) * 128 + kb + bkof);
                asm volatile("ldmatrix.sync.aligned.m8n8.x4.shared.b16 {%0,%1,%2,%3}, [%4];"
                             : "=r"(b[nj*2][0]), "=r"(b[nj*2][1]),
                               "=r"(b[nj*2+1][0]), "=r"(b[nj*2+1][1])
                             : "r"(addr));
            }
            #pragma unroll
            for (int mi = 0; mi < 4; mi++)
                #pragma unroll
                for (int ni = 0; ni < 8; ni++) {
                    asm volatile(
                        "mma.sync.aligned.m16n8k16.row.col.f32.f16.f16.f32 "
                        "{%0,%1,%2,%3}, {%4,%5,%6,%7}, {%8,%9}, {%0,%1,%2,%3};"
                        : "+f"(acc[mi][ni][0]), "+f"(acc[mi][ni][1]),
                          "+f"(acc[mi][ni][2]), "+f"(acc[mi][ni][3])
                        : "r"(a[mi][0]), "r"(a[mi][1]), "r"(a[mi][2]), "r"(a[mi][3]),
                          "r"(b[ni][0]), "r"(b[ni][1]));
                }
        }
    }

    // -------- fused epilogue: column sum of squares over this CTA's 128 rows --------
    const int way = m0 / MS;
    float* cs = colsum + ((size_t)t * WAY + way) * NPAD + n0;
    #pragma unroll
    for (int ni = 0; ni < 8; ni++) {
        float v0 = 0.f, v1 = 0.f;
        #pragma unroll
        for (int mi = 0; mi < 4; mi++) {
            v0 += acc[mi][ni][0] * acc[mi][ni][0] + acc[mi][ni][2] * acc[mi][ni][2];
            v1 += acc[mi][ni][1] * acc[mi][ni][1] + acc[mi][ni][3] * acc[mi][ni][3];
        }
        #pragma unroll
        for (int o = 4; o < 32; o <<= 1) {
            v0 += __shfl_xor_sync(~0u, v0, o);
            v1 += __shfl_xor_sync(~0u, v1, o);
        }
        if (gid == 0) {
            int col = wn * 64 + ni * 8 + tig * 2;
            atomicAdd(&cs[col], v0);       // two warps (wm=0/1) accumulate same cols
            atomicAdd(&cs[col + 1], v1);
        }
    }
}

// ---------------- kernel 5: /99, LeakyReLU(0.2), conv1d(k=stride=100), +bias ----------------
__global__ void final_kernel(const float* __restrict__ colsum, const float* __restrict__ cw,
                             const float* __restrict__ cb, float* __restrict__ out) {
    int wid  = (blockIdx.x * blockDim.x + threadIdx.x) >> 5;
    int lane = threadIdx.x & 31;
    if (wid >= T * WQ * WAY) return;
    int w = wid % WAY;
    int q = (wid / WAY) % WQ;
    int t = wid / (WAY * WQ);
    const float* cs = colsum + ((size_t)t * WAY + w) * NPAD + q * HW;
    float v = 0.f;
    #pragma unroll
    for (int i = 0; i < 4; i++) {
        int n = lane + 32 * i;
        if (n < HW) {
            float x = cs[n] * (1.0f / 99.0f);
            x = (x >= 0.f) ? x : 0.2f * x;
            v += x * cw[n];
        }
    }
    #pragma unroll
    for (int o = 16; o; o >>= 1) v += __shfl_xor_sync(~0u, v, o);
    if (!lane) out[wid] = v + cb[0];
}

// ---------------- launch ----------------
extern "C" void kernel_launch(void* const* d_in, const int* in_sizes, int n_in,
                              void* d_out, int out_size) {
    const float* qf = (const float*)d_in[0];
    const float* sf = (const float*)d_in[1];
    const float* cw = (const float*)d_in[2];
    const float* cb = (const float*)d_in[3];
    float* out = (float*)d_out;

    __half *dS, *dQ;
    float *dMS, *dCS;
    cudaGetSymbolAddress((void**)&dS,  g_S16);
    cudaGetSymbolAddress((void**)&dQ,  g_Q16);
    cudaGetSymbolAddress((void**)&dMS, g_meanS);
    cudaGetSymbolAddress((void**)&dCS, g_colsum);

    // 1) fused prep: support means + pads + zero colsum
    prep_kernel<<<MEAN_BLOCKS + PAD_BLOCKS + ZERO_BLOCKS, 256>>>(sf, dMS, dS, dQ, dCS);
    // 2) center+transpose S -> fp16
    center_s_kernel<<<T * WS * (C / 64), 256>>>(sf, dMS, dS);
    // 3) center(fused mean)+transpose Q -> fp16
    center_q_kernel<<<T * WQ * (C / 64), 256>>>(qf, dQ);
    // 4) GEMM + fused sum-of-squares   (4th launch -> ncu capture slot)
    cudaFuncSetAttribute(gemm_hmma_kernel, cudaFuncAttributeMaxDynamicSharedMemorySize, SMEM_TOTAL);
    dim3 grid(NPAD / BN, MTOT / BM, T);   // (60, 20, 4)
    gemm_hmma_kernel<<<grid, 128, SMEM_TOTAL>>>(dS, dQ, dCS);
    // 5) final score
    int warps = T * WQ * WAY;
    final_kernel<<<(warps * 32 + 255) / 256, 256>>>(dCS, cw, cb, out);
}